// round 2
// baseline (speedup 1.0000x reference)
#include <cuda_runtime.h>
#include <cstdint>

#define NB 8
#define NC 64
#define NH 256
#define NW 512
#define NK 9
#define BHW (NB * NH * NW)          // 1,048,576
#define W8 (NW / 8)                 // 64

// Scratch: P[k][b][y][x] = sum_c W[c,k] * F[b,c,y,x]   (37.75 MB, static device alloc)
__device__ float g_P[(size_t)NK * BHW];

// Packed f32x2 FMA (sm_100+): d = a*b + c on two lanes at once.
#define FMA_F32X2(d, a, b, c) \
    asm("fma.rn.f32x2 %0, %1, %2, %3;" : "=l"(d) : "l"(a), "l"(b), "l"(c))

// ---------------------------------------------------------------------------
// Pass 1: channel reduction. Each thread owns 8 consecutive x for one (b,y),
// loops c=0..63, accumulating 9 tap-planes in registers (f32x2 quads).
// 2x LDG.128 + 9 LDS.64 + 36 FFMA2 per channel iteration.
// ---------------------------------------------------------------------------
__global__ void __launch_bounds__(256) pass1_kernel(
    const float* __restrict__ feature,   // [B, C, H, W]
    const float* __restrict__ weight)    // [1, C, 3, 3] -> [C, 9]
{
    // Duplicated weights in shared: wdup[c*9+k] = (w, w) for direct f32x2 use.
    __shared__ float2 wdup[NC * NK];
    for (int i = threadIdx.x; i < NC * NK; i += 256) {
        float wv = weight[i];
        wdup[i] = make_float2(wv, wv);
    }
    __syncthreads();

    int g = blockIdx.x * 256 + threadIdx.x;      // [0, B*H*W/8)
    int x8 = g % W8;                              // x/8
    int yb = g / W8;                              // b*H + y

    // feature base in ulonglong2 (=float4) units; thread reads 2 adjacent float4s
    const ulonglong2* fptr =
        (const ulonglong2*)feature +
        ((size_t)(yb / NH) * NC * NH + (yb % NH)) * (NW / 4) + (size_t)x8 * 2;
    const size_t cs = (size_t)NH * (NW / 4);      // per-channel stride in float4 units

    unsigned long long acc[NK][4];
#pragma unroll
    for (int k = 0; k < NK; ++k) {
        acc[k][0] = 0ull; acc[k][1] = 0ull; acc[k][2] = 0ull; acc[k][3] = 0ull;
    }

#pragma unroll 2
    for (int c = 0; c < NC; ++c) {
        ulonglong2 u0 = fptr[(size_t)c * cs];         // floats x8..x8+3
        ulonglong2 u1 = fptr[(size_t)c * cs + 1];     // floats x8+4..x8+7
        const unsigned long long* wp =
            (const unsigned long long*)(wdup + c * NK);
#pragma unroll
        for (int k = 0; k < NK; ++k) {
            unsigned long long w = wp[k];
            FMA_F32X2(acc[k][0], u0.x, w, acc[k][0]);
            FMA_F32X2(acc[k][1], u0.y, w, acc[k][1]);
            FMA_F32X2(acc[k][2], u1.x, w, acc[k][2]);
            FMA_F32X2(acc[k][3], u1.y, w, acc[k][3]);
        }
    }

    // Store: P[k][yb][x8*8 .. +7] as 2x 16B stores per tap
    size_t pbase = (size_t)yb * NW + (size_t)x8 * 8;
#pragma unroll
    for (int k = 0; k < NK; ++k) {
        ulonglong2* dst = (ulonglong2*)(g_P + (size_t)k * BHW + pbase);
        ulonglong2 v0; v0.x = acc[k][0]; v0.y = acc[k][1];
        ulonglong2 v1; v1.x = acc[k][2]; v1.y = acc[k][3];
        dst[0] = v0;
        dst[1] = v1;
    }
}

// ---------------------------------------------------------------------------
// Pass 2: tap gather + 2x2 upsample. One thread per (b,h,w); grid.y = batch.
// Indices staged per-block in shared (stride-9 reads are bank-conflict-free).
// 9 independent gathers per thread (MLP 9), 1M threads total.
// ---------------------------------------------------------------------------
__global__ void __launch_bounds__(256) pass2_kernel(
    const int* __restrict__ gi,    // [H, W, 9]
    const int* __restrict__ gj,    // [H, W, 9]
    float* __restrict__ out)       // [B, 1, 2H, 2W]
{
    __shared__ int sgi[256 * NK];
    __shared__ int sgj[256 * NK];

    int hw0 = blockIdx.x * 256;
    for (int i = threadIdx.x; i < 256 * NK; i += 256) {
        sgi[i] = gi[(size_t)hw0 * NK + i];
        sgj[i] = gj[(size_t)hw0 * NK + i];
    }
    __syncthreads();

    int b = blockIdx.y;
    int hw = hw0 + threadIdx.x;
    int h = hw / NW;
    int w = hw % NW;
    int sb = threadIdx.x * NK;

    float acc = 0.0f;
#pragma unroll
    for (int k = 0; k < NK; ++k) {
        int y = sgi[sb + k];
        int x = sgj[sb + k];
        acc += g_P[(size_t)k * BHW + ((size_t)b * NH + y) * NW + x];
    }

    // out viewed as float2: [B][2H][NW] (row of 2W floats = NW float2)
    float2 v = make_float2(acc, acc);
    float2* o2 = (float2*)out;
    size_t row0 = ((size_t)b * (2 * NH) + 2 * h) * NW + w;
    o2[row0] = v;
    o2[row0 + NW] = v;
}

// ---------------------------------------------------------------------------
// Launch: graph-capturable, allocation-free.
// Inputs (metadata order): feature f32, weight f32, gi i32, gj i32.
// ---------------------------------------------------------------------------
extern "C" void kernel_launch(void* const* d_in, const int* in_sizes, int n_in,
                              void* d_out, int out_size)
{
    const float* feature = (const float*)d_in[0];
    const float* weight  = (const float*)d_in[1];
    const int*   gi      = (const int*)d_in[2];
    const int*   gj      = (const int*)d_in[3];
    float*       out     = (float*)d_out;

    // Pass 1: B*H*W/8 threads = 131072 -> 512 blocks of 256
    pass1_kernel<<<BHW / 8 / 256, 256>>>(feature, weight);
    // Pass 2: one thread per (b,h,w): grid (512, 8) x 256
    dim3 g2(NH * NW / 256, NB);
    pass2_kernel<<<g2, 256>>>(gi, gj, out);
}

// round 3
// speedup vs baseline: 1.1952x; 1.1952x over previous
#include <cuda_runtime.h>
#include <cstdint>

#define NB 8
#define NC 64
#define NH 256
#define NW 512
#define NK 9
#define BHW (NB * NH * NW)          // 1,048,576
#define W4 (NW / 4)                 // 128

// Scratch: P[k][b][y][x] = sum_c W[c,k] * F[b,c,y,x]   (37.75 MB, static device alloc)
__device__ float g_P[(size_t)NK * BHW];

// Packed f32x2 FMA (sm_100+): d = a*b + c on two lanes at once.
#define FMA_F32X2(d, a, b, c) \
    asm("fma.rn.f32x2 %0, %1, %2, %3;" : "=l"(d) : "l"(a), "l"(b), "l"(c))

// ---------------------------------------------------------------------------
// Pass 1: channel reduction. Each thread owns 4 consecutive x for one (b,y).
// Channels processed in pairs: per pair, 2x LDG.128 feature + 9x LDS.128
// weights (each LDS.128 = duplicated pair {w_c, w_c, w_c1, w_c1}) + 36 FFMA2.
// ---------------------------------------------------------------------------
__global__ void __launch_bounds__(256) pass1_kernel(
    const float* __restrict__ feature,   // [B, C, H, W]
    const float* __restrict__ weight)    // [1, C, 3, 3] -> [C, 9]
{
    // sw4[k][cc] = {w[2cc][k], w[2cc][k], w[2cc+1][k], w[2cc+1][k]}
    __shared__ float4 sw4[NK][NC / 2];
    for (int i = threadIdx.x; i < NK * (NC / 2); i += 256) {
        int k  = i % NK;
        int cc = i / NK;
        float w0 = weight[(2 * cc + 0) * NK + k];
        float w1 = weight[(2 * cc + 1) * NK + k];
        sw4[k][cc] = make_float4(w0, w0, w1, w1);
    }
    __syncthreads();

    int g = blockIdx.x * 256 + threadIdx.x;      // [0, B*H*W/4)
    int x4u = g % W4;                             // x/4
    int yb  = g / W4;                             // b*H + y

    // feature base in ulonglong2 (=float4) units
    const ulonglong2* fptr =
        (const ulonglong2*)feature + ((size_t)(yb / NH) * NC * NH + (yb % NH)) * W4 + x4u;
    const size_t cs = (size_t)NH * W4;            // per-channel stride in float4 units

    unsigned long long acc_lo[NK], acc_hi[NK];
#pragma unroll
    for (int k = 0; k < NK; ++k) { acc_lo[k] = 0ull; acc_hi[k] = 0ull; }

#pragma unroll 2
    for (int cc = 0; cc < NC / 2; ++cc) {
        ulonglong2 f0 = fptr[(size_t)(2 * cc + 0) * cs];   // channel 2cc
        ulonglong2 f1 = fptr[(size_t)(2 * cc + 1) * cs];   // channel 2cc+1
#pragma unroll
        for (int k = 0; k < NK; ++k) {
            // one LDS.128: {w0,w0,w1,w1}
            const ulonglong2 wp = *(const ulonglong2*)&sw4[k][cc];
            FMA_F32X2(acc_lo[k], f0.x, wp.x, acc_lo[k]);
            FMA_F32X2(acc_hi[k], f0.y, wp.x, acc_hi[k]);
            FMA_F32X2(acc_lo[k], f1.x, wp.y, acc_lo[k]);
            FMA_F32X2(acc_hi[k], f1.y, wp.y, acc_hi[k]);
        }
    }

    // Store: P[k][yb][x4*4 .. +3] as one 16B store per tap
    size_t pbase = (size_t)yb * NW + (size_t)x4u * 4;
#pragma unroll
    for (int k = 0; k < NK; ++k) {
        ulonglong2 v; v.x = acc_lo[k]; v.y = acc_hi[k];
        *(ulonglong2*)(g_P + (size_t)k * BHW + pbase) = v;
    }
}

// ---------------------------------------------------------------------------
// Pass 2: tap gather + 2x2 upsample. One thread per (h,w) x 4 batches;
// grid.y=2 covers the 8 batches. Indices loaded once, reused across 4 batches
// (MLP: 18 index LDGs then 36 independent P gathers).
// ---------------------------------------------------------------------------
__global__ void __launch_bounds__(256) pass2_kernel(
    const int* __restrict__ gi,    // [H, W, 9]
    const int* __restrict__ gj,    // [H, W, 9]
    float* __restrict__ out)       // [B, 1, 2H, 2W]
{
    int g = blockIdx.x * 256 + threadIdx.x;      // [0, H*W)
    int h = g / NW;
    int w = g % NW;
    int ib = g * NK;
    int b0 = blockIdx.y * 4;                      // batch group: 0 or 4

    int ys[NK], xs[NK];
#pragma unroll
    for (int k = 0; k < NK; ++k) ys[k] = gi[ib + k];
#pragma unroll
    for (int k = 0; k < NK; ++k) xs[k] = gj[ib + k];

    float acc[4] = {0.f, 0.f, 0.f, 0.f};
#pragma unroll
    for (int k = 0; k < NK; ++k) {
        const float* Pk = g_P + (size_t)k * BHW
                        + ((size_t)b0 * NH + ys[k]) * NW + xs[k];
#pragma unroll
        for (int j = 0; j < 4; ++j)
            acc[j] += Pk[(size_t)j * NH * NW];
    }

    // out viewed as float2: [B][2H][NW] (row of 2W floats = NW float2)
    float2* o2 = (float2*)out;
#pragma unroll
    for (int j = 0; j < 4; ++j) {
        float2 v = make_float2(acc[j], acc[j]);
        size_t row0 = ((size_t)(b0 + j) * (2 * NH) + 2 * h) * NW + w;
        o2[row0] = v;
        o2[row0 + NW] = v;
    }
}

// ---------------------------------------------------------------------------
// Launch: graph-capturable, allocation-free.
// Inputs (metadata order): feature f32, weight f32, gi i32, gj i32.
// ---------------------------------------------------------------------------
extern "C" void kernel_launch(void* const* d_in, const int* in_sizes, int n_in,
                              void* d_out, int out_size)
{
    const float* feature = (const float*)d_in[0];
    const float* weight  = (const float*)d_in[1];
    const int*   gi      = (const int*)d_in[2];
    const int*   gj      = (const int*)d_in[3];
    float*       out     = (float*)d_out;

    // Pass 1: B*H*W/4 threads = 262144 -> 1024 blocks of 256
    pass1_kernel<<<BHW / 4 / 256, 256>>>(feature, weight);
    // Pass 2: thread per (h,w) x 4 batches; grid (512, 2) x 256
    dim3 g2(NH * NW / 256, 2);
    pass2_kernel<<<g2, 256>>>(gi, gj, out);
}

// round 4
// speedup vs baseline: 1.6764x; 1.4026x over previous
#include <cuda_runtime.h>
#include <cstdint>

#define NB 8
#define NC 64
#define NH 256
#define NW 512
#define NK 9
#define BHW (NB * NH * NW)          // 1,048,576
#define W4 (NW / 4)                 // 128

typedef unsigned long long ull;

// Scratch: P[k][b][y][x] = sum_c W[c,k] * F[b,c,y,x]   (37.75 MB, static device alloc)
__device__ float g_P[(size_t)NK * BHW];

// Packed f32x2 FMA (sm_100+): d = a*b + c on two lanes at once.
#define FMA_F32X2(d, a, b, c) \
    asm("fma.rn.f32x2 %0, %1, %2, %3;" : "=l"(d) : "l"(a), "l"(b), "l"(c))

// ---------------------------------------------------------------------------
// Pass 1: channel reduction. Each thread owns 4 consecutive x for one (b,y).
// Channels processed in blocks of 8 with explicit 8-deep load staging
// (8 back-to-back 16B streaming loads -> MLP 8 per warp), then the FMA block
// consumes them in load order. 24 warps/SM x 8 x 128B ~ 24.5KB in flight.
// ---------------------------------------------------------------------------
__global__ void __launch_bounds__(256, 3) pass1_kernel(
    const float* __restrict__ feature,   // [B, C, H, W]
    const float* __restrict__ weight)    // [1, C, 3, 3] -> [C, 9]
{
    // Duplicated weights in shared: wdup[c*9+k] = (w, w) for direct f32x2 use.
    __shared__ float2 wdup[NC * NK];
    for (int i = threadIdx.x; i < NC * NK; i += 256) {
        float wv = weight[i];
        wdup[i] = make_float2(wv, wv);
    }
    __syncthreads();

    int g = blockIdx.x * 256 + threadIdx.x;      // [0, B*H*W/4)
    int x4u = g % W4;                             // x/4
    int yb  = g / W4;                             // b*H + y

    const float* fbase = feature
        + ((size_t)(yb / NH) * NC * NH + (yb % NH)) * NW + (size_t)x4u * 4;

    ull acc_lo[NK], acc_hi[NK];
#pragma unroll
    for (int k = 0; k < NK; ++k) { acc_lo[k] = 0ull; acc_hi[k] = 0ull; }

    for (int c0 = 0; c0 < NC; c0 += 8) {
        ull f[8][2];
        // 8 back-to-back streaming 16B loads (evict-first; no reuse in pass 1)
#pragma unroll
        for (int j = 0; j < 8; ++j) {
            const float* p = fbase + (size_t)(c0 + j) * (NH * NW);
            asm volatile("ld.global.cs.v2.u64 {%0, %1}, [%2];"
                         : "=l"(f[j][0]), "=l"(f[j][1]) : "l"(p));
        }
        // Consume in load order: scoreboard waits only on the oldest load.
#pragma unroll
        for (int j = 0; j < 8; ++j) {
            const ull* wp = (const ull*)(wdup + (c0 + j) * NK);
#pragma unroll
            for (int k = 0; k < NK; ++k) {
                ull w = wp[k];
                FMA_F32X2(acc_lo[k], f[j][0], w, acc_lo[k]);
                FMA_F32X2(acc_hi[k], f[j][1], w, acc_hi[k]);
            }
        }
    }

    // Store: P[k][yb][x4*4 .. +3] as one 16B store per tap
    size_t pbase = (size_t)yb * NW + (size_t)x4u * 4;
#pragma unroll
    for (int k = 0; k < NK; ++k) {
        ulonglong2 v; v.x = acc_lo[k]; v.y = acc_hi[k];
        *(ulonglong2*)(g_P + (size_t)k * BHW + pbase) = v;
    }
}

// ---------------------------------------------------------------------------
// Pass 2: tap gather + 2x2 upsample. One thread per (h,w) x 4 batches;
// grid.y=2 covers the 8 batches. Indices loaded once, reused across 4 batches.
// ---------------------------------------------------------------------------
__global__ void __launch_bounds__(256) pass2_kernel(
    const int* __restrict__ gi,    // [H, W, 9]
    const int* __restrict__ gj,    // [H, W, 9]
    float* __restrict__ out)       // [B, 1, 2H, 2W]
{
    int g = blockIdx.x * 256 + threadIdx.x;      // [0, H*W)
    int h = g / NW;
    int w = g % NW;
    int ib = g * NK;
    int b0 = blockIdx.y * 4;                      // batch group: 0 or 4

    int ys[NK], xs[NK];
#pragma unroll
    for (int k = 0; k < NK; ++k) ys[k] = gi[ib + k];
#pragma unroll
    for (int k = 0; k < NK; ++k) xs[k] = gj[ib + k];

    float acc[4] = {0.f, 0.f, 0.f, 0.f};
#pragma unroll
    for (int k = 0; k < NK; ++k) {
        const float* Pk = g_P + (size_t)k * BHW
                        + ((size_t)b0 * NH + ys[k]) * NW + xs[k];
#pragma unroll
        for (int j = 0; j < 4; ++j)
            acc[j] += Pk[(size_t)j * NH * NW];
    }

    // out viewed as float2: [B][2H][NW] (row of 2W floats = NW float2)
    float2* o2 = (float2*)out;
#pragma unroll
    for (int j = 0; j < 4; ++j) {
        float2 v = make_float2(acc[j], acc[j]);
        size_t row0 = ((size_t)(b0 + j) * (2 * NH) + 2 * h) * NW + w;
        o2[row0] = v;
        o2[row0 + NW] = v;
    }
}

// ---------------------------------------------------------------------------
// Launch: graph-capturable, allocation-free.
// Inputs (metadata order): feature f32, weight f32, gi i32, gj i32.
// ---------------------------------------------------------------------------
extern "C" void kernel_launch(void* const* d_in, const int* in_sizes, int n_in,
                              void* d_out, int out_size)
{
    const float* feature = (const float*)d_in[0];
    const float* weight  = (const float*)d_in[1];
    const int*   gi      = (const int*)d_in[2];
    const int*   gj      = (const int*)d_in[3];
    float*       out     = (float*)d_out;

    // Pass 1: B*H*W/4 threads = 262144 -> 1024 blocks of 256
    pass1_kernel<<<BHW / 4 / 256, 256>>>(feature, weight);
    // Pass 2: thread per (h,w) x 4 batches; grid (512, 2) x 256
    dim3 g2(NH * NW / 256, 2);
    pass2_kernel<<<g2, 256>>>(gi, gj, out);
}